// round 13
// baseline (speedup 1.0000x reference)
#include <cuda_runtime.h>
#include <cuda_fp16.h>
#include <cstdint>

#define THREADS 480      // 15 independent warps, 1 CTA/SM, 136-reg cap
#define NW      15
#define ROWS    16       // edges per warp-chunk
#define FS      100      // fp32 stage row stride (floats); 400B ≡ 16 mod 128
#define W1_H    120      // W1 fp16 stride (halves)
#define W2_H    72       // W2 fp16 stride (halves)

// smem: stage 15w*2buf*16r*400B = 192000; W1 15360; W2 4608; b1 256; b2 128
#define STG_BYTES 192000
#define SM_BYTES  (STG_BYTES + 15360 + 4608 + 256 + 128)

__device__ __forceinline__ uint32_t f2_to_h2(float x, float y) {
    __half2 h = __floats2half2_rn(x, y);
    return *(uint32_t*)&h;
}
__device__ __forceinline__ uint32_t s2u(const void* p) {
    uint32_t a;
    asm("{ .reg .u64 t; cvta.to.shared.u64 t, %1; cvt.u32.u64 %0, t; }" : "=r"(a) : "l"(p));
    return a;
}
__device__ __forceinline__ void cp16(uint32_t dst, const void* src, int sz) {
    asm volatile("cp.async.cg.shared.global [%0], [%1], 16, %2;"
                 :: "r"(dst), "l"(src), "r"(sz) : "memory");
}
__device__ __forceinline__ void ldm_x4(uint32_t* r, uint32_t addr) {
    asm volatile("ldmatrix.sync.aligned.m8n8.x4.shared.b16 {%0,%1,%2,%3}, [%4];"
        : "=r"(r[0]), "=r"(r[1]), "=r"(r[2]), "=r"(r[3]) : "r"(addr));
}
__device__ __forceinline__ void mma_f16(float* d, const uint32_t* a, const uint32_t* b) {
    asm volatile(
        "mma.sync.aligned.m16n8k16.row.col.f32.f16.f16.f32 "
        "{%0,%1,%2,%3}, {%4,%5,%6,%7}, {%8,%9}, {%0,%1,%2,%3};"
        : "+f"(d[0]), "+f"(d[1]), "+f"(d[2]), "+f"(d[3])
        : "r"(a[0]), "r"(a[1]), "r"(a[2]), "r"(a[3]), "r"(b[0]), "r"(b[1]));
}

extern "C" __global__ void __launch_bounds__(THREADS, 1)
edge_mlp_p(const float* __restrict__ src, const float* __restrict__ dst,
           const float* __restrict__ ea, const float* __restrict__ u,
           const int* __restrict__ batch,
           const float* __restrict__ W1, const float* __restrict__ b1,
           const float* __restrict__ W2, const float* __restrict__ b2,
           float* __restrict__ out, int E, int nchunks)
{
    extern __shared__ char smraw[];
    float*  stg = (float*)smraw;                             // [15][2][16][FS]
    __half* w1s = (__half*)(smraw + STG_BYTES);              // [64 n][W1_H k]
    __half* w2s = (__half*)(smraw + STG_BYTES + 15360);      // [32 n][W2_H k]
    float*  b1s = (float*)(smraw + STG_BYTES + 15360 + 4608);
    float*  b2s = b1s + 64;

    const int t    = threadIdx.x;
    const int w    = t >> 5;
    const int lane = t & 31;
    const int gid  = lane >> 2;   // 0..7
    const int ctid = lane & 3;    // 0..3

    // ---- stage W1/W2 [n][k] halves + biases (once per CTA) ----
    {
        const float2* w12 = (const float2*)W1;   // 64*56 float2
        for (int i = t; i < 3584; i += THREADS) {
            int n = i / 56, k2 = i % 56;
            float2 v = w12[i];
            *(uint32_t*)&w1s[n * W1_H + 2 * k2] = f2_to_h2(v.x, v.y);
        }
        const float2* w22 = (const float2*)W2;   // 32*32 float2
        for (int i = t; i < 1024; i += THREADS) {
            int n = i / 32, k2 = i % 32;
            float2 v = w22[i];
            *(uint32_t*)&w2s[n * W2_H + 2 * k2] = f2_to_h2(v.x, v.y);
        }
        if (t < 64) b1s[t] = b1[t];
        if (t >= 64 && t < 96) b2s[t - 64] = b2[t - 64];
    }
    __syncthreads();

    float* buf0 = stg + w * (2 * ROWS * FS);
    float* buf1 = buf0 + ROWS * FS;
    const uint32_t buf0_u = s2u(buf0);
    const uint32_t buf1_u = s2u(buf1);
    const uint32_t w1_u   = s2u(w1s);
    const uint32_t w2_u   = s2u(w2s);

    // ldmatrix per-lane offsets (B operand pattern)
    const int np    = ((lane >> 4) & 1) * 8 + (lane & 7);
    const int bkp   = ((lane >> 3) & 1) * 16;
    const int boff1 = np * (W1_H * 2) + bkp;
    const int boff2 = np * (W2_H * 2) + bkp;

    // ---- persistent W1 fragments: n = 0..31 (7 ks x 2 ntp x 4 regs = 56) ----
    uint32_t w1p[7][2][4];
    #pragma unroll
    for (int ks = 0; ks < 7; ks++)
        #pragma unroll
        for (int ntp = 0; ntp < 2; ntp++)
            ldm_x4(w1p[ks][ntp], w1_u + 16 * ntp * (W1_H * 2) + boff1 + ks * 32);

    // cp.async staging of src|dst|ea: 16 rows x 24 16B-segs = 384 segs, 12/lane
    auto stage = [&](uint32_t bufu, int ch) {
        const int e0 = ch * ROWS;
        #pragma unroll
        for (int i = 0; i < 12; i++) {
            int s = lane + 32 * i;
            int r = s / 24, c = s % 24;
            int e = e0 + r;
            int ec = e < E ? e : E - 1;
            const float4* a4 = (c < 8) ? (const float4*)src
                             : (c < 16) ? (const float4*)dst
                                        : (const float4*)ea;
            const void* sp = (const void*)(a4 + (size_t)ec * 8 + (c & 7));
            cp16(bufu + (uint32_t)(r * (FS * 4) + c * 16), sp, e < E ? 16 : 0);
        }
        asm volatile("cp.async.commit_group;" ::: "memory");
    };

    int ch = blockIdx.x * NW + w;
    const int step = gridDim.x * NW;

    int bA = 0, bB = 0;
    if (ch < nchunks) {
        stage(buf0_u, ch);
        int eA = ch * ROWS + gid, eB = eA + 8;
        bA = batch[eA < E ? eA : E - 1];
        bB = batch[eB < E ? eB : E - 1];
    }

    int pb = 0;
    for (; ch < nchunks; ch += step) {
        const int e0 = ch * ROWS;
        const int nch = ch + step;

        // u[batch] fragments (uses current bA/bB; overlaps staging below)
        uint32_t au[4];
        {
            float2 a0 = *(const float2*)&u[(size_t)bA * 16 + 2 * ctid];
            float2 a1 = *(const float2*)&u[(size_t)bB * 16 + 2 * ctid];
            float2 a2 = *(const float2*)&u[(size_t)bA * 16 + 8 + 2 * ctid];
            float2 a3 = *(const float2*)&u[(size_t)bB * 16 + 8 + 2 * ctid];
            au[0] = f2_to_h2(a0.x, a0.y);
            au[1] = f2_to_h2(a1.x, a1.y);
            au[2] = f2_to_h2(a2.x, a2.y);
            au[3] = f2_to_h2(a3.x, a3.y);
        }

        int nA = bA, nB = bB;
        if (nch < nchunks) {
            stage(pb ? buf0_u : buf1_u, nch);
            int eA = nch * ROWS + gid, eB = eA + 8;
            nA = batch[eA < E ? eA : E - 1];
            nB = batch[eB < E ? eB : E - 1];
            asm volatile("cp.async.wait_group 1;" ::: "memory");
        } else {
            asm volatile("cp.async.wait_group 0;" ::: "memory");
        }
        __syncwarp();

        const float* bp = pb ? buf1 : buf0;

        // ===== GEMM1: [16x112] @ [112x64]; n0-31 from w1p regs, n32-63 via ldm =====
        float acc[8][4];
        #pragma unroll
        for (int nt = 0; nt < 8; nt++)
            #pragma unroll
            for (int q = 0; q < 4; q++) acc[nt][q] = 0.f;

        #pragma unroll
        for (int ks = 0; ks < 7; ks++) {
            uint32_t a[4];
            if (ks < 6) {
                int k0 = 16 * ks + 2 * ctid;
                float2 f0 = *(const float2*)&bp[gid * FS + k0];
                float2 f1 = *(const float2*)&bp[(gid + 8) * FS + k0];
                float2 f2 = *(const float2*)&bp[gid * FS + k0 + 8];
                float2 f3 = *(const float2*)&bp[(gid + 8) * FS + k0 + 8];
                a[0] = f2_to_h2(f0.x, f0.y);
                a[1] = f2_to_h2(f1.x, f1.y);
                a[2] = f2_to_h2(f2.x, f2.y);
                a[3] = f2_to_h2(f3.x, f3.y);
            } else {
                a[0] = au[0]; a[1] = au[1]; a[2] = au[2]; a[3] = au[3];
            }
            // n = 0..31 from persistent registers
            mma_f16(acc[0], a, &w1p[ks][0][0]);
            mma_f16(acc[1], a, &w1p[ks][0][2]);
            mma_f16(acc[2], a, &w1p[ks][1][0]);
            mma_f16(acc[3], a, &w1p[ks][1][2]);
            // n = 32..63 via ldmatrix
            #pragma unroll
            for (int ntp = 2; ntp < 4; ntp++) {
                uint32_t b[4];
                ldm_x4(b, w1_u + 16 * ntp * (W1_H * 2) + boff1 + ks * 32);
                mma_f16(acc[2 * ntp],     a, &b[0]);
                mma_f16(acc[2 * ntp + 1], a, &b[2]);
            }
        }

        // ===== fused epilogue1 + GEMM2 (W2 B-frags via ldmatrix) =====
        float acc2[4][4];
        #pragma unroll
        for (int nt = 0; nt < 4; nt++)
            #pragma unroll
            for (int q = 0; q < 4; q++) acc2[nt][q] = 0.f;

        #pragma unroll
        for (int ks = 0; ks < 4; ks++) {
            float2 bAv = *(const float2*)&b1s[16 * ks + 2 * ctid];
            float2 bBv = *(const float2*)&b1s[16 * ks + 8 + 2 * ctid];
            uint32_t a2[4];
            a2[0] = f2_to_h2(fmaxf(acc[2*ks][0] + bAv.x, 0.f),
                             fmaxf(acc[2*ks][1] + bAv.y, 0.f));
            a2[1] = f2_to_h2(fmaxf(acc[2*ks][2] + bAv.x, 0.f),
                             fmaxf(acc[2*ks][3] + bAv.y, 0.f));
            a2[2] = f2_to_h2(fmaxf(acc[2*ks+1][0] + bBv.x, 0.f),
                             fmaxf(acc[2*ks+1][1] + bBv.y, 0.f));
            a2[3] = f2_to_h2(fmaxf(acc[2*ks+1][2] + bBv.x, 0.f),
                             fmaxf(acc[2*ks+1][3] + bBv.y, 0.f));
            #pragma unroll
            for (int ntp = 0; ntp < 2; ntp++) {
                uint32_t b[4];
                ldm_x4(b, w2_u + 16 * ntp * (W2_H * 2) + boff2 + ks * 32);
                mma_f16(acc2[2 * ntp],     a2, &b[0]);
                mma_f16(acc2[2 * ntp + 1], a2, &b[2]);
            }
        }

        // ---- epilogue 2: bias + store ----
        {
            int eA2 = e0 + gid, eB2 = e0 + 8 + gid;
            #pragma unroll
            for (int nt = 0; nt < 4; nt++) {
                int c = 8 * nt + 2 * ctid;
                float2 bv = *(const float2*)&b2s[c];
                if (eA2 < E) {
                    float2 v;
                    v.x = acc2[nt][0] + bv.x;
                    v.y = acc2[nt][1] + bv.y;
                    *(float2*)&out[(size_t)eA2 * 32 + c] = v;
                }
                if (eB2 < E) {
                    float2 v;
                    v.x = acc2[nt][2] + bv.x;
                    v.y = acc2[nt][3] + bv.y;
                    *(float2*)&out[(size_t)eB2 * 32 + c] = v;
                }
            }
        }

        bA = nA; bB = nB;
        pb ^= 1;
    }
}

extern "C" void kernel_launch(void* const* d_in, const int* in_sizes, int n_in,
                              void* d_out, int out_size) {
    const float* src   = (const float*)d_in[0];
    const float* dst   = (const float*)d_in[1];
    const float* ea    = (const float*)d_in[2];
    const float* u     = (const float*)d_in[3];
    const int*   batch = (const int*)d_in[4];
    const float* W1    = (const float*)d_in[5];
    const float* b1    = (const float*)d_in[6];
    const float* W2    = (const float*)d_in[7];
    const float* b2    = (const float*)d_in[8];
    float*       out   = (float*)d_out;

    int E = in_sizes[0] / 32;
    int nchunks = (E + ROWS - 1) / ROWS;

    int nsm = 148;
    cudaDeviceGetAttribute(&nsm, cudaDevAttrMultiProcessorCount, 0);
    int grid = 2 * nsm;
    int maxg = (nchunks + NW - 1) / NW;
    if (grid > maxg) grid = maxg;

    cudaFuncSetAttribute(edge_mlp_p,
                         cudaFuncAttributeMaxDynamicSharedMemorySize, SM_BYTES);
    edge_mlp_p<<<grid, THREADS, SM_BYTES>>>(src, dst, ea, u, batch,
                                            W1, b1, W2, b2, out, E, nchunks);
}

// round 14
// speedup vs baseline: 1.5832x; 1.5832x over previous
#include <cuda_runtime.h>
#include <cuda_fp16.h>
#include <cstdint>

#define THREADS 512      // 16 independent warps, 1 CTA/SM, 128-reg cap
#define NW      16
#define ROWS    32       // edges per warp-chunk (m = 2x16)
#define RING    4        // cp.async slab ring depth (power of 2)
#define SLAB_F  24       // slab row stride in floats (96B): gid*96 mod 128 = {0,32,64,96} x2
#define SLAB_B  (32 * SLAB_F * 4)   // 3072 B per slab
#define W1_H    120      // W1 fp16 stride (halves)
#define W2_H    72       // W2 fp16 stride (halves)

// smem: slabs 16w*4*3072 = 196608; W1 15360; W2 4608; b1 256; b2 128
#define STG_BYTES (NW * RING * SLAB_B)
#define SM_BYTES  (STG_BYTES + 15360 + 4608 + 256 + 128)

__device__ __forceinline__ uint32_t f2_to_h2(float x, float y) {
    __half2 h = __floats2half2_rn(x, y);
    return *(uint32_t*)&h;
}
__device__ __forceinline__ uint32_t s2u(const void* p) {
    uint32_t a;
    asm("{ .reg .u64 t; cvta.to.shared.u64 t, %1; cvt.u32.u64 %0, t; }" : "=r"(a) : "l"(p));
    return a;
}
__device__ __forceinline__ void cp16(uint32_t dst, const void* src, int sz) {
    asm volatile("cp.async.cg.shared.global [%0], [%1], 16, %2;"
                 :: "r"(dst), "l"(src), "r"(sz) : "memory");
}
__device__ __forceinline__ void ldm_x4(uint32_t* r, uint32_t addr) {
    asm volatile("ldmatrix.sync.aligned.m8n8.x4.shared.b16 {%0,%1,%2,%3}, [%4];"
        : "=r"(r[0]), "=r"(r[1]), "=r"(r[2]), "=r"(r[3]) : "r"(addr));
}
__device__ __forceinline__ void mma_f16(float* d, const uint32_t* a, const uint32_t* b) {
    asm volatile(
        "mma.sync.aligned.m16n8k16.row.col.f32.f16.f16.f32 "
        "{%0,%1,%2,%3}, {%4,%5,%6,%7}, {%8,%9}, {%0,%1,%2,%3};"
        : "+f"(d[0]), "+f"(d[1]), "+f"(d[2]), "+f"(d[3])
        : "r"(a[0]), "r"(a[1]), "r"(a[2]), "r"(a[3]), "r"(b[0]), "r"(b[1]));
}

extern "C" __global__ void __launch_bounds__(THREADS, 1)
edge_mlp_ring(const float* __restrict__ src, const float* __restrict__ dst,
              const float* __restrict__ ea, const float* __restrict__ u,
              const int* __restrict__ batch,
              const float* __restrict__ W1, const float* __restrict__ b1,
              const float* __restrict__ W2, const float* __restrict__ b2,
              float* __restrict__ out, int E, int nchunks)
{
    extern __shared__ char smraw[];
    float*  stg = (float*)smraw;                             // [16][RING][32][SLAB_F]
    __half* w1s = (__half*)(smraw + STG_BYTES);              // [64 n][W1_H k]
    __half* w2s = (__half*)(smraw + STG_BYTES + 15360);      // [32 n][W2_H k]
    float*  b1s = (float*)(smraw + STG_BYTES + 15360 + 4608);
    float*  b2s = b1s + 64;

    const int t    = threadIdx.x;
    const int w    = t >> 5;
    const int lane = t & 31;
    const int gid  = lane >> 2;   // 0..7
    const int ctid = lane & 3;    // 0..3

    // ---- stage W1/W2 [n][k] halves + biases (once per CTA) ----
    {
        const float2* w12 = (const float2*)W1;   // 64*56 float2
        for (int i = t; i < 3584; i += THREADS) {
            int n = i / 56, k2 = i % 56;
            float2 v = w12[i];
            *(uint32_t*)&w1s[n * W1_H + 2 * k2] = f2_to_h2(v.x, v.y);
        }
        const float2* w22 = (const float2*)W2;   // 32*32 float2
        for (int i = t; i < 1024; i += THREADS) {
            int n = i / 32, k2 = i % 32;
            float2 v = w22[i];
            *(uint32_t*)&w2s[n * W2_H + 2 * k2] = f2_to_h2(v.x, v.y);
        }
        if (t < 64) b1s[t] = b1[t];
        if (t >= 64 && t < 96) b2s[t - 64] = b2[t - 64];
    }
    __syncthreads();

    float* wslab = stg + w * (RING * SLAB_B / 4);
    const uint32_t wslab_u = s2u(wslab);
    const uint32_t w1_u    = s2u(w1s);
    const uint32_t w2_u    = s2u(w2s);

    // ldmatrix per-lane offsets (B operand pattern)
    const int np    = ((lane >> 4) & 1) * 8 + (lane & 7);
    const int bkp   = ((lane >> 3) & 1) * 16;
    const int boff1 = np * (W1_H * 2) + bkp;
    const int boff2 = np * (W2_H * 2) + bkp;

    // cp.async one slab: 32 rows x 16 floats of one source array (4 segs/row)
    const int sr = lane >> 2;        // seg row group base (lane/4)... mapping below
    auto stage_slab = [&](int slot, int e0s, int ks) {
        const float* arr = (ks < 2) ? src : (ks < 4) ? dst : ea;
        const int kof = (ks & 1) * 16;
        const uint32_t sbase = wslab_u + (uint32_t)slot * SLAB_B;
        #pragma unroll
        for (int i = 0; i < 4; i++) {
            int s = lane + 32 * i;          // 0..127
            int r = s >> 2, c = s & 3;
            int e = e0s + r;
            int ec = e < E ? e : E - 1;
            cp16(sbase + (uint32_t)(r * (SLAB_F * 4) + c * 16),
                 (const void*)(arr + (size_t)ec * 32 + kof + c * 4),
                 e < E ? 16 : 0);
        }
        asm volatile("cp.async.commit_group;" ::: "memory");
    };
    (void)sr;

    int ch = blockIdx.x * NW + w;
    const int step = gridDim.x * NW;
    if (ch >= nchunks) return;

    // issue state: global slab counter decomposed
    int issue_e0 = ch * ROWS;
    int issue_ks = 0;
    int slot_i   = 0;    // issue slot = consume slot (refill same after use)

    // prologue: fill RING slabs
    #pragma unroll
    for (int i = 0; i < RING; i++) {
        stage_slab(i, issue_e0, issue_ks);
        if (++issue_ks == 6) { issue_ks = 0; issue_e0 += step * ROWS; }
    }

    // batch indices for first chunk (rows: mt*16 + gid, +8)
    int bA[2], bB[2];
    #pragma unroll
    for (int mt = 0; mt < 2; mt++) {
        int eA = ch * ROWS + 16 * mt + gid, eB = eA + 8;
        bA[mt] = batch[eA < E ? eA : E - 1];
        bB[mt] = batch[eB < E ? eB : E - 1];
    }

    for (; ch < nchunks; ch += step) {
        const int e0 = ch * ROWS;
        const int nch = ch + step;

        // u[batch] fragments (current chunk) + next-chunk batch prefetch
        uint32_t au[2][4];
        #pragma unroll
        for (int mt = 0; mt < 2; mt++) {
            float2 a0 = *(const float2*)&u[(size_t)bA[mt] * 16 + 2 * ctid];
            float2 a1 = *(const float2*)&u[(size_t)bB[mt] * 16 + 2 * ctid];
            float2 a2 = *(const float2*)&u[(size_t)bA[mt] * 16 + 8 + 2 * ctid];
            float2 a3 = *(const float2*)&u[(size_t)bB[mt] * 16 + 8 + 2 * ctid];
            au[mt][0] = f2_to_h2(a0.x, a0.y);
            au[mt][1] = f2_to_h2(a1.x, a1.y);
            au[mt][2] = f2_to_h2(a2.x, a2.y);
            au[mt][3] = f2_to_h2(a3.x, a3.y);
        }
        if (nch < nchunks) {
            #pragma unroll
            for (int mt = 0; mt < 2; mt++) {
                int eA = nch * ROWS + 16 * mt + gid, eB = eA + 8;
                bA[mt] = batch[eA < E ? eA : E - 1];
                bB[mt] = batch[eB < E ? eB : E - 1];
            }
        }

        // ===== GEMM1: [32x112] @ [112x64]; ks 0..5 from slab ring, ks 6 = u =====
        float acc[2][8][4];
        #pragma unroll
        for (int mt = 0; mt < 2; mt++)
            #pragma unroll
            for (int nt = 0; nt < 8; nt++)
                #pragma unroll
                for (int q = 0; q < 4; q++) acc[mt][nt][q] = 0.f;

        #pragma unroll
        for (int ks = 0; ks < 6; ks++) {
            asm volatile("cp.async.wait_group %0;" :: "n"(RING - 1) : "memory");
            __syncwarp();

            const float* sl = wslab + slot_i * (SLAB_B / 4);
            uint32_t a[2][4];
            #pragma unroll
            for (int mt = 0; mt < 2; mt++) {
                int r0 = 16 * mt + gid;
                float2 f0 = *(const float2*)&sl[r0 * SLAB_F + 2 * ctid];
                float2 f1 = *(const float2*)&sl[(r0 + 8) * SLAB_F + 2 * ctid];
                float2 f2 = *(const float2*)&sl[r0 * SLAB_F + 2 * ctid + 8];
                float2 f3 = *(const float2*)&sl[(r0 + 8) * SLAB_F + 2 * ctid + 8];
                a[mt][0] = f2_to_h2(f0.x, f0.y);
                a[mt][1] = f2_to_h2(f1.x, f1.y);
                a[mt][2] = f2_to_h2(f2.x, f2.y);
                a[mt][3] = f2_to_h2(f3.x, f3.y);
            }
            #pragma unroll
            for (int ntp = 0; ntp < 4; ntp++) {
                uint32_t b[4];
                ldm_x4(b, w1_u + 16 * ntp * (W1_H * 2) + boff1 + ks * 32);
                #pragma unroll
                for (int mt = 0; mt < 2; mt++) {
                    mma_f16(acc[mt][2 * ntp],     a[mt], &b[0]);
                    mma_f16(acc[mt][2 * ntp + 1], a[mt], &b[2]);
                }
            }

            __syncwarp();   // all lanes done reading slot before refill lands
            stage_slab(slot_i, issue_e0, issue_ks);
            if (++issue_ks == 6) { issue_ks = 0; issue_e0 += step * ROWS; }
            slot_i = (slot_i + 1) & (RING - 1);
        }
        // ks = 6: u[batch] from registers
        #pragma unroll
        for (int ntp = 0; ntp < 4; ntp++) {
            uint32_t b[4];
            ldm_x4(b, w1_u + 16 * ntp * (W1_H * 2) + boff1 + 6 * 32);
            #pragma unroll
            for (int mt = 0; mt < 2; mt++) {
                mma_f16(acc[mt][2 * ntp],     au[mt], &b[0]);
                mma_f16(acc[mt][2 * ntp + 1], au[mt], &b[2]);
            }
        }

        // ===== fused epilogue1 + GEMM2 =====
        float acc2[2][4][4];
        #pragma unroll
        for (int mt = 0; mt < 2; mt++)
            #pragma unroll
            for (int nt = 0; nt < 4; nt++)
                #pragma unroll
                for (int q = 0; q < 4; q++) acc2[mt][nt][q] = 0.f;

        #pragma unroll
        for (int ks = 0; ks < 4; ks++) {
            float2 bAv = *(const float2*)&b1s[16 * ks + 2 * ctid];
            float2 bBv = *(const float2*)&b1s[16 * ks + 8 + 2 * ctid];
            uint32_t bw[2][4];
            #pragma unroll
            for (int ntp = 0; ntp < 2; ntp++)
                ldm_x4(bw[ntp], w2_u + 16 * ntp * (W2_H * 2) + boff2 + ks * 32);
            #pragma unroll
            for (int mt = 0; mt < 2; mt++) {
                uint32_t a2[4];
                a2[0] = f2_to_h2(fmaxf(acc[mt][2*ks][0] + bAv.x, 0.f),
                                 fmaxf(acc[mt][2*ks][1] + bAv.y, 0.f));
                a2[1] = f2_to_h2(fmaxf(acc[mt][2*ks][2] + bAv.x, 0.f),
                                 fmaxf(acc[mt][2*ks][3] + bAv.y, 0.f));
                a2[2] = f2_to_h2(fmaxf(acc[mt][2*ks+1][0] + bBv.x, 0.f),
                                 fmaxf(acc[mt][2*ks+1][1] + bBv.y, 0.f));
                a2[3] = f2_to_h2(fmaxf(acc[mt][2*ks+1][2] + bBv.x, 0.f),
                                 fmaxf(acc[mt][2*ks+1][3] + bBv.y, 0.f));
                #pragma unroll
                for (int ntp = 0; ntp < 2; ntp++) {
                    mma_f16(acc2[mt][2 * ntp],     a2, &bw[ntp][0]);
                    mma_f16(acc2[mt][2 * ntp + 1], a2, &bw[ntp][2]);
                }
            }
        }

        // ---- epilogue 2: bias + store ----
        #pragma unroll
        for (int mt = 0; mt < 2; mt++) {
            int eA2 = e0 + 16 * mt + gid, eB2 = eA2 + 8;
            #pragma unroll
            for (int nt = 0; nt < 4; nt++) {
                int c = 8 * nt + 2 * ctid;
                float2 bv = *(const float2*)&b2s[c];
                if (eA2 < E) {
                    float2 v;
                    v.x = acc2[mt][nt][0] + bv.x;
                    v.y = acc2[mt][nt][1] + bv.y;
                    *(float2*)&out[(size_t)eA2 * 32 + c] = v;
                }
                if (eB2 < E) {
                    float2 v;
                    v.x = acc2[mt][nt][2] + bv.x;
                    v.y = acc2[mt][nt][3] + bv.y;
                    *(float2*)&out[(size_t)eB2 * 32 + c] = v;
                }
            }
        }
    }
}

extern "C" void kernel_launch(void* const* d_in, const int* in_sizes, int n_in,
                              void* d_out, int out_size) {
    const float* src   = (const float*)d_in[0];
    const float* dst   = (const float*)d_in[1];
    const float* ea    = (const float*)d_in[2];
    const float* u     = (const float*)d_in[3];
    const int*   batch = (const int*)d_in[4];
    const float* W1    = (const float*)d_in[5];
    const float* b1    = (const float*)d_in[6];
    const float* W2    = (const float*)d_in[7];
    const float* b2    = (const float*)d_in[8];
    float*       out   = (float*)d_out;

    int E = in_sizes[0] / 32;
    int nchunks = (E + ROWS - 1) / ROWS;

    int nsm = 148;
    cudaDeviceGetAttribute(&nsm, cudaDevAttrMultiProcessorCount, 0);
    int grid = 2 * nsm;
    int maxg = (nchunks + NW - 1) / NW;
    if (grid > maxg) grid = maxg;

    cudaFuncSetAttribute(edge_mlp_ring,
                         cudaFuncAttributeMaxDynamicSharedMemorySize, SM_BYTES);
    edge_mlp_ring<<<grid, THREADS, SM_BYTES>>>(src, dst, ea, u, batch,
                                               W1, b1, W2, b2, out, E, nchunks);
}